// round 8
// baseline (speedup 1.0000x reference)
#include <cuda_runtime.h>
#include <cuda_bf16.h>
#include <math.h>

// ---------------- problem constants ----------------
#define BB   16
#define SS   32
#define NTT  2029
#define NN   256
#define PIX  (NN*NN)            // 65536
#define IMG  (BB*PIX)           // 1048576

// ---------------- scratch (device globals; referenced ONLY from device code) --
__device__ float g_rec [BB*PIX];                 // 4 MB
__device__ float g_h0  [BB*64 *128*128];         // 64 MB
__device__ float g_h1  [BB*128*64 *64 ];         // 32 MB
__device__ float g_h2  [BB*256*32 *32 ];         // 16 MB
__device__ float g_h3  [BB*512*16 *16 ];         // 8 MB
__device__ float g_h4  [BB*512*8  *8  ];         // 2 MB
__device__ float g_u4  [BB*512*16 *16 ];         // 8 MB
__device__ float g_u3  [BB*256*32 *32 ];         // 16 MB
__device__ float g_u2  [BB*128*64 *64 ];         // 32 MB
__device__ float g_u1  [BB*64 *128*128];         // 64 MB
__device__ float g_wpack[4*512*512*4];           // 16 MB (per-parity repacked deconv weights)
__device__ float g_mm[2];
__device__ float g_scale[512];
__device__ float g_shift[512];

// ---------------- packed fp32x2 FMA (Blackwell FFMA2) ----------------
__device__ __forceinline__ void fma2(unsigned long long& acc,
                                     unsigned long long a,
                                     unsigned long long b)
{
    asm("fma.rn.f32x2 %0, %1, %2, %0;" : "+l"(acc) : "l"(a), "l"(b));
}
__device__ __forceinline__ float lo32(unsigned long long v)
{ return __uint_as_float((unsigned)(v & 0xffffffffu)); }
__device__ __forceinline__ float hi32(unsigned long long v)
{ return __uint_as_float((unsigned)(v >> 32)); }

// ---------------- backprojection (bit-exact R4/R6 form — DO NOT TOUCH) -------
__global__ void k_backproject(const float* __restrict__ sig,
                              const float* __restrict__ trans)
{
    int idx = blockIdx.x * blockDim.x + threadIdx.x;
    if (idx >= PIX) return;
    int j = idx & 255;
    int i = idx >> 8;

    const float startf = -0.0125f;
    const float stopf  =  0.0125f;
    float stepj = __fdiv_rn((float)j, 255.0f);
    float stepi = __fdiv_rn((float)i, 255.0f);
    float cj = __fadd_rn(__fmul_rn(startf, __fsub_rn(1.0f, stepj)),
                         __fmul_rn(stopf,  stepj));
    float ci = __fadd_rn(__fmul_rn(startf, __fsub_rn(1.0f, stepi)),
                         __fmul_rn(stopf,  stepi));

    float acc[BB];
#pragma unroll
    for (int b = 0; b < BB; b++) acc[b] = 0.f;

    for (int s = 0; s < SS; s++) {
        float dx = __fsub_rn(cj, __ldg(&trans[2*s+0]));
        float dy = __fsub_rn(ci, __ldg(&trans[2*s+1]));
        float dd = __fadd_rn(__fmul_rn(dx, dx), __fmul_rn(dy, dy));
        float d  = __fsqrt_rn(dd);
        float v  = __fadd_rn(__fsub_rn(__fdiv_rn(__fmul_rn(d, 40000000.0f),
                                                 1572.0f),
                                       113.0f),
                             1.0f);
        int t = (int)rintf(v);
        t = max(0, min(t, NTT-1));
        const float* sp = sig + (size_t)t * SS + s;
#pragma unroll
        for (int b = 0; b < BB; b++)
            acc[b] += __ldg(sp + (size_t)b * NTT * SS);
    }
#pragma unroll
    for (int b = 0; b < BB; b++)
        g_rec[(size_t)b * PIX + idx] = acc[b] * (1.0f / 32.0f);
}

// ---------------- global min/max ----------------
__device__ void atomicMinF(float* a, float v) {
    int old = __float_as_int(*a);
    while (v < __int_as_float(old)) {
        int prev = atomicCAS((int*)a, old, __float_as_int(v));
        if (prev == old) break;
        old = prev;
    }
}
__device__ void atomicMaxF(float* a, float v) {
    int old = __float_as_int(*a);
    while (v > __int_as_float(old)) {
        int prev = atomicCAS((int*)a, old, __float_as_int(v));
        if (prev == old) break;
        old = prev;
    }
}
__global__ void k_minmax_init() { g_mm[0] = INFINITY; g_mm[1] = -INFINITY; }

__global__ void k_minmax_reduce()
{
    float mn = INFINITY, mx = -INFINITY;
    for (int i = blockIdx.x * blockDim.x + threadIdx.x; i < IMG; i += gridDim.x * blockDim.x) {
        float v = g_rec[i];
        mn = fminf(mn, v);
        mx = fmaxf(mx, v);
    }
    __shared__ float smn[256], smx[256];
    int t = threadIdx.x;
    smn[t] = mn; smx[t] = mx;
    __syncthreads();
    for (int o = 128; o > 0; o >>= 1) {
        if (t < o) { smn[t] = fminf(smn[t], smn[t+o]); smx[t] = fmaxf(smx[t], smx[t+o]); }
        __syncthreads();
    }
    if (t == 0) { atomicMinF(&g_mm[0], smn[0]); atomicMaxF(&g_mm[1], smx[0]); }
}

__global__ void k_normalize(float* __restrict__ out_rec, int copy_out)
{
    int i = blockIdx.x * blockDim.x + threadIdx.x;
    if (i >= IMG) return;
    float mn = g_mm[0], mx = g_mm[1];
    float v = __fdiv_rn(__fsub_rn(g_rec[i], mn), __fsub_rn(mx, mn));
    g_rec[i] = v;
    if (copy_out) out_rec[i] = v;
}

// =====================================================================
// conv stride-2 k4 p1 — implicit GEMM v1.6 (FFMA2)
// 64x64 tile, 256 threads, 4x4 micro-tile, double-buffered smem,
// A stored DUPLICATED ({a,a} pairs) so packed operands load directly;
// inner loop = 8 fma.rn.f32x2 per k-step.
// Per-output accumulation order identical to v1.5 (cci asc, taps inner).
// =====================================================================
template<int Cin, int Hi, int Wi, int Cout, int ACT>
__device__ __forceinline__ void conv_v16(const float* __restrict__ in,
                                         const float* __restrict__ w,
                                         float* __restrict__ out)
{
    constexpr int Ho = Hi >> 1, Wo = Wi >> 1;
    constexpr int HoWo = Ho * Wo;
    constexpr int HiWi = Hi * Wi;
    const int m0 = blockIdx.y * 64;
    const int p0 = blockIdx.x * 64;

    __shared__ __align__(16) float As[2][16][132];   // duplicated pairs: col 2n,2n+1 = A[n]
    __shared__ __align__(16) float Bs[2][16][68];

    const int tid  = threadIdx.x;
    const int kk   = tid & 15;      // staging: tap index / compute: col group
    const int rowq = tid >> 4;      // staging: row group / compute: row group
    const int ky = kk >> 2, kx = kk & 3;
    const int tx = kk, ty = rowq;

    int woff[4], bofs[4];
#pragma unroll
    for (int q = 0; q < 4; q++) {
        int n = rowq + 16 * q;
        woff[q] = (m0 + n) * Cin * 16 + kk;
        int p = p0 + n;
        int b = p / HoWo; int r = p - b * HoWo;
        int y = r / Wo;   int x = r - y * Wo;
        int iy = 2*y - 1 + ky, ix = 2*x - 1 + kx;
        bool v = iy >= 0 && iy < Hi && ix >= 0 && ix < Wi;
        bofs[q] = v ? (b * Cin * HiWi + iy * Wi + ix) : -1;
    }

    float aR[4], bR[4];
    // prologue: stage chunk 0
#pragma unroll
    for (int q = 0; q < 4; q++) {
        aR[q] = __ldg(w + woff[q]);
        float v = 0.f;
        if (bofs[q] >= 0) {
            v = __ldg(in + bofs[q]);
            if (ACT) v = (v >= 0.f) ? v : 0.2f * v;
        }
        bR[q] = v;
    }
#pragma unroll
    for (int q = 0; q < 4; q++) {
        *(float2*)&As[0][kk][2*(rowq + 16*q)] = make_float2(aR[q], aR[q]);
        Bs[0][kk][rowq + 16*q] = bR[q];
    }
    __syncthreads();

    unsigned long long acc2[4][2];
#pragma unroll
    for (int i = 0; i < 4; i++) { acc2[i][0] = 0ull; acc2[i][1] = 0ull; }

    int buf = 0;
    for (int cci = 0; cci < Cin; cci++) {
        const bool more = (cci + 1 < Cin);
        if (more) {
            const float* wp = w + (size_t)(cci + 1) * 16;
            const float* ip = in + (size_t)(cci + 1) * HiWi;
#pragma unroll
            for (int q = 0; q < 4; q++) {
                aR[q] = __ldg(wp + woff[q]);
                float v = 0.f;
                if (bofs[q] >= 0) {
                    v = __ldg(ip + bofs[q]);
                    if (ACT) v = (v >= 0.f) ? v : 0.2f * v;
                }
                bR[q] = v;
            }
        }
#pragma unroll
        for (int k = 0; k < 16; k++) {
            ulonglong2 a01 = *(const ulonglong2*)(&As[buf][k][8*ty]);     // {a0,a0},{a1,a1}
            ulonglong2 a23 = *(const ulonglong2*)(&As[buf][k][8*ty + 4]); // {a2,a2},{a3,a3}
            ulonglong2 bp  = *(const ulonglong2*)(&Bs[buf][k][4*tx]);     // {b0,b1},{b2,b3}
            fma2(acc2[0][0], a01.x, bp.x); fma2(acc2[0][1], a01.x, bp.y);
            fma2(acc2[1][0], a01.y, bp.x); fma2(acc2[1][1], a01.y, bp.y);
            fma2(acc2[2][0], a23.x, bp.x); fma2(acc2[2][1], a23.x, bp.y);
            fma2(acc2[3][0], a23.y, bp.x); fma2(acc2[3][1], a23.y, bp.y);
        }
        if (more) {
            int nb = buf ^ 1;
#pragma unroll
            for (int q = 0; q < 4; q++) {
                *(float2*)&As[nb][kk][2*(rowq + 16*q)] = make_float2(aR[q], aR[q]);
                Bs[nb][kk][rowq + 16*q] = bR[q];
            }
            __syncthreads();
            buf = nb;
        }
    }

    // epilogue: float4 stores (64 | HoWo for all layers, quads stay in-image)
#pragma unroll
    for (int i = 0; i < 4; i++) {
        int m = m0 + ty * 4 + i;
        int p = p0 + tx * 4;
        int b = p / HoWo; int r = p - b * HoWo;
        float4 v = make_float4(lo32(acc2[i][0]), hi32(acc2[i][0]),
                               lo32(acc2[i][1]), hi32(acc2[i][1]));
        *(float4*)(&out[(size_t)(b * Cout + m) * HoWo + r]) = v;
    }
}

__global__ void __launch_bounds__(256,3) k_conv_d0(const float* __restrict__ w)
{ conv_v16<1,256,256,64,0>(g_rec, w, g_h0); }
__global__ void __launch_bounds__(256,3) k_conv_d1(const float* __restrict__ w)
{ conv_v16<64,128,128,128,1>(g_h0, w, g_h1); }
__global__ void __launch_bounds__(256,3) k_conv_d2(const float* __restrict__ w)
{ conv_v16<128,64,64,256,1>(g_h1, w, g_h2); }
__global__ void __launch_bounds__(256,3) k_conv_d3(const float* __restrict__ w)
{ conv_v16<256,32,32,512,1>(g_h2, w, g_h3); }
__global__ void __launch_bounds__(256,3) k_conv_d4(const float* __restrict__ w)
{ conv_v16<512,16,16,512,1>(g_h3, w, g_h4); }

// ---------------- deconv weight repack (per-parity) ----------------
__global__ void k_repack(const float* __restrict__ w, int Cin, int Cout)
{
    int idx = blockIdx.x * blockDim.x + threadIdx.x;
    int total = 4 * Cout * Cin * 4;
    if (idx >= total) return;
    int t  = idx & 3;
    int tmp = idx >> 2;
    int ci = tmp % Cin; tmp /= Cin;
    int m  = tmp % Cout;
    int pz = tmp / Cout;
    int py = pz >> 1, px = pz & 1;
    int di = t >> 1,  dj = t & 1;
    int ky = py ? (1 + 2*di) : (2*di);
    int kx = px ? (1 + 2*dj) : (2*dj);
    g_wpack[idx] = w[(((size_t)ci * Cout + m) * 4 + (3 - ky)) * 4 + (3 - kx)];
}

// =====================================================================
// transposed conv stride-2 k4 p2 — parity implicit GEMM v1.6 (FFMA2)
// =====================================================================
template<int Cin, int C1, int Hi, int Wi, int Cout>
__device__ __forceinline__ void deconv_v16(const float* __restrict__ in1,
                                           const float* __restrict__ in2,
                                           float* __restrict__ out)
{
    constexpr int HiWi = Hi * Wi;
    constexpr int Wo = 2 * Wi;
    constexpr int HoWo = 4 * HiWi;
    constexpr int C2 = Cin - C1;
    constexpr int NCH = Cin / 4;
    const int pz = blockIdx.z;
    const int py = pz >> 1, px = pz & 1;
    const int m0 = blockIdx.y * 64;
    const int n0 = blockIdx.x * 64;

    __shared__ __align__(16) float As[2][16][132];   // duplicated pairs
    __shared__ __align__(16) float Bs[2][16][68];

    const int tid  = threadIdx.x;
    const int kk   = tid & 15;      // cil*4 + t
    const int rowq = tid >> 4;
    const int cil = kk >> 2, t = kk & 3;
    const int di = t >> 1, dj = t & 1;
    const int tx = kk, ty = rowq;

    int woff[4], pixq[4], bq[4];
#pragma unroll
    for (int q = 0; q < 4; q++) {
        int n = n0 + rowq + 16 * q;
        int b = n / HiWi; int r = n - b * HiWi;
        int yy = r / Wi;  int xx = r - yy * Wi;
        int i = py ? (yy + di) : (yy - 1 + di);
        int j = px ? (xx + dj) : (xx - 1 + dj);
        bool v = i >= 0 && i < Hi && j >= 0 && j < Wi;
        pixq[q] = v ? (i * Wi + j) : -1;
        bq[q] = b;
        int m = m0 + rowq + 16 * q;
        woff[q] = ((pz * Cout + m) * Cin + cil) * 4 + t;
    }

    float aR[4], bR[4];
    // prologue: chunk 0 (ci = cil)
#pragma unroll
    for (int q = 0; q < 4; q++) {
        aR[q] = g_wpack[woff[q]];
        float v = 0.f;
        if (pixq[q] >= 0) {
            const float* src = (cil < C1)
                ? in1 + (size_t)(bq[q] * C1 + cil) * HiWi
                : in2 + (size_t)(bq[q] * C2 + (cil - C1)) * HiWi;
            v = fmaxf(__ldg(src + pixq[q]), 0.f);
        }
        bR[q] = v;
    }
#pragma unroll
    for (int q = 0; q < 4; q++) {
        *(float2*)&As[0][kk][2*(rowq + 16*q)] = make_float2(aR[q], aR[q]);
        Bs[0][kk][rowq + 16*q] = bR[q];
    }
    __syncthreads();

    unsigned long long acc2[4][2];
#pragma unroll
    for (int i = 0; i < 4; i++) { acc2[i][0] = 0ull; acc2[i][1] = 0ull; }

    int buf = 0;
    for (int s = 0; s < NCH; s++) {
        const bool more = (s + 1 < NCH);
        if (more) {
            int ci = 4 * (s + 1) + cil;
#pragma unroll
            for (int q = 0; q < 4; q++) {
                aR[q] = g_wpack[woff[q] + (s + 1) * 16];
                float v = 0.f;
                if (pixq[q] >= 0) {
                    const float* src = (ci < C1)
                        ? in1 + (size_t)(bq[q] * C1 + ci) * HiWi
                        : in2 + (size_t)(bq[q] * C2 + (ci - C1)) * HiWi;
                    v = fmaxf(__ldg(src + pixq[q]), 0.f);
                }
                bR[q] = v;
            }
        }
#pragma unroll
        for (int k = 0; k < 16; k++) {
            ulonglong2 a01 = *(const ulonglong2*)(&As[buf][k][8*ty]);
            ulonglong2 a23 = *(const ulonglong2*)(&As[buf][k][8*ty + 4]);
            ulonglong2 bp  = *(const ulonglong2*)(&Bs[buf][k][4*tx]);
            fma2(acc2[0][0], a01.x, bp.x); fma2(acc2[0][1], a01.x, bp.y);
            fma2(acc2[1][0], a01.y, bp.x); fma2(acc2[1][1], a01.y, bp.y);
            fma2(acc2[2][0], a23.x, bp.x); fma2(acc2[2][1], a23.x, bp.y);
            fma2(acc2[3][0], a23.y, bp.x); fma2(acc2[3][1], a23.y, bp.y);
        }
        if (more) {
            int nb = buf ^ 1;
#pragma unroll
            for (int q = 0; q < 4; q++) {
                *(float2*)&As[nb][kk][2*(rowq + 16*q)] = make_float2(aR[q], aR[q]);
                Bs[nb][kk][rowq + 16*q] = bR[q];
            }
            __syncthreads();
            buf = nb;
        }
    }

#pragma unroll
    for (int i = 0; i < 4; i++) {
        int m = m0 + ty * 4 + i;
        float accv[4] = {lo32(acc2[i][0]), hi32(acc2[i][0]),
                         lo32(acc2[i][1]), hi32(acc2[i][1])};
#pragma unroll
        for (int j = 0; j < 4; j++) {
            int n = n0 + tx * 4 + j;
            int b = n / HiWi; int r = n - b * HiWi;
            int yy = r / Wi;  int xx = r - yy * Wi;
            int y = 2 * yy + py, x = 2 * xx + px;
            out[(size_t)(b * Cout + m) * HoWo + y * Wo + x] = accv[j];
        }
    }
}

__global__ void __launch_bounds__(256,3) k_deconv_u4()
{ deconv_v16<512,512,8,8,512>(g_h4, g_h4, g_u4); }
__global__ void __launch_bounds__(256,3) k_deconv_u3()
{ deconv_v16<1024,512,16,16,256>(g_h3, g_u4, g_u3); }
__global__ void __launch_bounds__(256,3) k_deconv_u2()
{ deconv_v16<512,256,32,32,128>(g_h2, g_u3, g_u2); }
__global__ void __launch_bounds__(256,3) k_deconv_u1()
{ deconv_v16<256,128,64,64,64>(g_h1, g_u2, g_u1); }

// ---------------- batchnorm ----------------
template<int C, int HW>
__device__ __forceinline__ void bn_stats_body(const float* __restrict__ x,
                                              const float* __restrict__ g,
                                              const float* __restrict__ bet)
{
    int c = blockIdx.x;
    constexpr int per = BB * HW;
    double s = 0.0, s2 = 0.0;
    for (int i = threadIdx.x; i < per; i += blockDim.x) {
        int bb = i / HW; int r = i - bb * HW;
        float v = x[(size_t)(bb * C + c) * HW + r];
        s  += v;
        s2 += (double)v * (double)v;
    }
    __shared__ double sh1[256], sh2[256];
    int tidl = threadIdx.x;
    sh1[tidl] = s; sh2[tidl] = s2;
    __syncthreads();
    for (int o = 128; o > 0; o >>= 1) {
        if (tidl < o) { sh1[tidl] += sh1[tidl+o]; sh2[tidl] += sh2[tidl+o]; }
        __syncthreads();
    }
    if (tidl == 0) {
        double m   = sh1[0] / per;
        double var = sh2[0] / per - m * m;
        float sc = g[c] * (float)(1.0 / sqrt(var + 1e-5));
        g_scale[c] = sc;
        g_shift[c] = bet[c] - (float)m * sc;
    }
}

template<int C, int HW>
__device__ __forceinline__ void bn_apply_body(float* __restrict__ x)
{
    constexpr int total = BB * C * HW;
    int i = blockIdx.x * blockDim.x + threadIdx.x;
    if (i >= total) return;
    int c = (i / HW) % C;
    x[i] = x[i] * g_scale[c] + g_shift[c];
}

__global__ void k_bns_h1(const float* g, const float* b){ bn_stats_body<128,4096>(g_h1,g,b); }
__global__ void k_bna_h1(){ bn_apply_body<128,4096>(g_h1); }
__global__ void k_bns_h2(const float* g, const float* b){ bn_stats_body<256,1024>(g_h2,g,b); }
__global__ void k_bna_h2(){ bn_apply_body<256,1024>(g_h2); }
__global__ void k_bns_h3(const float* g, const float* b){ bn_stats_body<512,256>(g_h3,g,b); }
__global__ void k_bna_h3(){ bn_apply_body<512,256>(g_h3); }
__global__ void k_bns_u4(const float* g, const float* b){ bn_stats_body<512,256>(g_u4,g,b); }
__global__ void k_bna_u4(){ bn_apply_body<512,256>(g_u4); }
__global__ void k_bns_u3(const float* g, const float* b){ bn_stats_body<256,1024>(g_u3,g,b); }
__global__ void k_bna_u3(){ bn_apply_body<256,1024>(g_u3); }
__global__ void k_bns_u2(const float* g, const float* b){ bn_stats_body<128,4096>(g_u2,g,b); }
__global__ void k_bna_u2(){ bn_apply_body<128,4096>(g_u2); }
__global__ void k_bns_u1(const float* g, const float* b){ bn_stats_body<64,16384>(g_u1,g,b); }
__global__ void k_bna_u1(){ bn_apply_body<64,16384>(g_u1); }

// ---------------- final deconv u0: 2x2 output quad per thread ----------------
__global__ void k_deconv_u0(const float* __restrict__ w,     // (128,1,4,4)
                            const float* __restrict__ b0,
                            float* __restrict__ out)         // (16,1,256,256)
{
    __shared__ float ws[2048];
    for (int i = threadIdx.x; i < 2048; i += blockDim.x) ws[i] = w[i];
    __syncthreads();

    int idx = blockIdx.x * blockDim.x + threadIdx.x;   // over BB*128*128
    if (idx >= BB * 128 * 128) return;
    int xx = idx & 127;
    int yy = (idx >> 7) & 127;
    int b  = idx >> 14;

    const float* h0p = g_h0 + (size_t)b * 64 * 16384;
    const float* u1p = g_u1 + (size_t)b * 64 * 16384;

    float a00 = 0.f, a01 = 0.f, a10 = 0.f, a11 = 0.f;

    for (int ci = 0; ci < 128; ci++) {
        const float* src = (ci < 64) ? (h0p + ci * 16384)
                                     : (u1p + (ci - 64) * 16384);
        float v[3][3];
#pragma unroll
        for (int dy = 0; dy < 3; dy++) {
            int i = yy - 1 + dy;
#pragma unroll
            for (int dxx = 0; dxx < 3; dxx++) {
                int jx = xx - 1 + dxx;
                v[dy][dxx] = (i >= 0 && i < 128 && jx >= 0 && jx < 128)
                             ? fmaxf(__ldg(src + i * 128 + jx), 0.f) : 0.f;
            }
        }
        const float* wsr = ws + ci * 16;
#pragma unroll
        for (int di = 0; di < 2; di++)
#pragma unroll
            for (int dj = 0; dj < 2; dj++)
                a00 += v[di][dj] * wsr[(3 - 2*di) * 4 + (3 - 2*dj)];
#pragma unroll
        for (int di = 0; di < 2; di++)
#pragma unroll
            for (int dj = 0; dj < 2; dj++)
                a01 += v[di][dj+1] * wsr[(3 - 2*di) * 4 + (2 - 2*dj)];
#pragma unroll
        for (int di = 0; di < 2; di++)
#pragma unroll
            for (int dj = 0; dj < 2; dj++)
                a10 += v[di+1][dj] * wsr[(2 - 2*di) * 4 + (3 - 2*dj)];
#pragma unroll
        for (int di = 0; di < 2; di++)
#pragma unroll
            for (int dj = 0; dj < 2; dj++)
                a11 += v[di+1][dj+1] * wsr[(2 - 2*di) * 4 + (2 - 2*dj)];
    }

    float bias = __ldg(&b0[0]);
    int base = b * PIX + (2 * yy) * 256 + 2 * xx;
    out[base]       = 1.0f / (1.0f + expf(-(a00 + bias)));
    out[base + 1]   = 1.0f / (1.0f + expf(-(a01 + bias)));
    out[base + 256] = 1.0f / (1.0f + expf(-(a10 + bias)));
    out[base + 257] = 1.0f / (1.0f + expf(-(a11 + bias)));
}

// ---------------- driver ----------------
extern "C" void kernel_launch(void* const* d_in, const int* in_sizes, int n_in,
                              void* d_out, int out_size)
{
    const float* sig   = (const float*)d_in[0];
    const float* trans = (const float*)d_in[1];
    const float* w_d0  = (const float*)d_in[2];
    const float* w_d1  = (const float*)d_in[3];
    const float* g_d1  = (const float*)d_in[4];
    const float* b_d1  = (const float*)d_in[5];
    const float* w_d2  = (const float*)d_in[6];
    const float* g_d2  = (const float*)d_in[7];
    const float* b_d2  = (const float*)d_in[8];
    const float* w_d3  = (const float*)d_in[9];
    const float* g_d3  = (const float*)d_in[10];
    const float* b_d3  = (const float*)d_in[11];
    const float* w_d4  = (const float*)d_in[12];
    const float* w_u4  = (const float*)d_in[13];
    const float* g_u4p = (const float*)d_in[14];
    const float* b_u4p = (const float*)d_in[15];
    const float* w_u3  = (const float*)d_in[16];
    const float* g_u3p = (const float*)d_in[17];
    const float* b_u3p = (const float*)d_in[18];
    const float* w_u2  = (const float*)d_in[19];
    const float* g_u2p = (const float*)d_in[20];
    const float* b_u2p = (const float*)d_in[21];
    const float* w_u1  = (const float*)d_in[22];
    const float* g_u1p = (const float*)d_in[23];
    const float* b_u1p = (const float*)d_in[24];
    const float* w_u0  = (const float*)d_in[25];
    const float* b_u0  = (const float*)d_in[26];

    float* outp = (float*)d_out;
    float* out_rec = outp + IMG;
    int copy_rec = (out_size >= 2 * IMG) ? 1 : 0;

    // 1. backprojection + normalization (rec)
    k_backproject<<<PIX / 256, 256>>>(sig, trans);
    k_minmax_init<<<1, 1>>>();
    k_minmax_reduce<<<256, 256>>>();
    k_normalize<<<(IMG + 255) / 256, 256>>>(out_rec, copy_rec);

    // 2. encoder (grid: x = Ptot/64, y = Cout/64; 256 threads)
    k_conv_d0<<<dim3(4096, 1), 256>>>(w_d0);
    k_conv_d1<<<dim3(1024, 2), 256>>>(w_d1);
    k_bns_h1<<<128, 256>>>(g_d1, b_d1);
    k_bna_h1<<<BB*128*4096/256, 256>>>();
    k_conv_d2<<<dim3(256,  4), 256>>>(w_d2);
    k_bns_h2<<<256, 256>>>(g_d2, b_d2);
    k_bna_h2<<<BB*256*1024/256, 256>>>();
    k_conv_d3<<<dim3(64,   8), 256>>>(w_d3);
    k_bns_h3<<<512, 256>>>(g_d3, b_d3);
    k_bna_h3<<<BB*512*256/256, 256>>>();
    k_conv_d4<<<dim3(16,   8), 256>>>(w_d4);

    // 3. decoder (grid: x = Ncls/64, y = Cout/64, z = parity; 256 threads)
    k_repack<<<(512*512*16 + 255)/256, 256>>>(w_u4, 512, 512);
    k_deconv_u4<<<dim3(16,  8, 4), 256>>>();
    k_bns_u4<<<512, 256>>>(g_u4p, b_u4p);
    k_bna_u4<<<BB*512*256/256, 256>>>();

    k_repack<<<(1024*256*16 + 255)/256, 256>>>(w_u3, 1024, 256);
    k_deconv_u3<<<dim3(64,  4, 4), 256>>>();
    k_bns_u3<<<256, 256>>>(g_u3p, b_u3p);
    k_bna_u3<<<BB*256*1024/256, 256>>>();

    k_repack<<<(512*128*16 + 255)/256, 256>>>(w_u2, 512, 128);
    k_deconv_u2<<<dim3(256, 2, 4), 256>>>();
    k_bns_u2<<<128, 256>>>(g_u2p, b_u2p);
    k_bna_u2<<<BB*128*4096/256, 256>>>();

    k_repack<<<(256*64*16 + 255)/256, 256>>>(w_u1, 256, 64);
    k_deconv_u1<<<dim3(1024, 1, 4), 256>>>();
    k_bns_u1<<<64, 256>>>(g_u1p, b_u1p);
    k_bna_u1<<<BB*64*16384/256, 256>>>();

    // 4. final layer: 2x2 quad per thread, fused bias + sigmoid
    k_deconv_u0<<<(BB*128*128 + 255) / 256, 256>>>(w_u0, b_u0, outp);
}